// round 4
// baseline (speedup 1.0000x reference)
#include <cuda_runtime.h>
#include <math.h>
#include <stdint.h>

// ---------------------------------------------------------------------------
// ASE block: B=16, DIM=256, H=W=64, KEY_DIM=16, HEADS=8, NH_KD=128, DH=256
//   k_means    : row/col means of x                     -> g_xm
//   k_projmean : q/k/v on means (+scale/bias/pos-embed) -> g_qkm
//   k_attnproj : axial attention + Wr/Wc projection     -> g_xrc
//   k_main     : fused per-pixel pipeline, TF32 tensor-core GEMMs (M=32/block)
// ---------------------------------------------------------------------------

#define NPIX 4096
#define SLICE (16*256*64)

__device__ float g_xm  [2*16*256*64];
__device__ float g_qkm [2*16*512*64];
__device__ float g_xrc [2*16*256*64];

// ---------------------------------------------------------------------------
__global__ void k_means(const float* __restrict__ x) {
    int bc = blockIdx.x;
    const float* xp = x + (size_t)bc * NPIX;
    int t = threadIdx.x;
    int warp = t >> 5, lane = t & 31;
    __shared__ float rowp[64][2];
    float colacc = 0.f;
    for (int h = 0; h < 64; h++) {
        float v = xp[h*64 + t];
        colacc += v;
        float s = v;
        s += __shfl_xor_sync(0xffffffffu, s, 16);
        s += __shfl_xor_sync(0xffffffffu, s, 8);
        s += __shfl_xor_sync(0xffffffffu, s, 4);
        s += __shfl_xor_sync(0xffffffffu, s, 2);
        s += __shfl_xor_sync(0xffffffffu, s, 1);
        if (lane == 0) rowp[h][warp] = s;
    }
    __syncthreads();
    float rm = (rowp[t][0] + rowp[t][1]) * (1.f/64.f);
    g_xm[(size_t)bc*64 + t]         = rm;
    g_xm[SLICE + (size_t)bc*64 + t] = colacc * (1.f/64.f);
}

__device__ __forceinline__ float pe_interp(const float* pe, int chan, int p) {
    float pos = fminf(fmaxf((p + 0.5f)*0.25f - 0.5f, 0.f), 15.f);
    int   i0  = (int)pos;
    int   i1  = min(i0 + 1, 15);
    float w   = pos - (float)i0;
    return pe[chan*16 + i0]*(1.f - w) + pe[chan*16 + i1]*w;
}

// ---------------------------------------------------------------------------
// K2a: project means. grid (32 = 16 rowchunks x 2 colhalves, 2 branch, 16 b)
// ---------------------------------------------------------------------------
__global__ void k_projmean(
    const float* __restrict__ Wq, const float* __restrict__ sq, const float* __restrict__ bq,
    const float* __restrict__ Wk, const float* __restrict__ sk, const float* __restrict__ bk,
    const float* __restrict__ Wv, const float* __restrict__ sv, const float* __restrict__ bv,
    const float* __restrict__ pe_rq, const float* __restrict__ pe_rk,
    const float* __restrict__ pe_cq, const float* __restrict__ pe_ck)
{
    int bx = blockIdx.x;
    int chunk = bx >> 1, half = bx & 1;
    int branch = blockIdx.y;
    int b      = blockIdx.z;
    int tid = threadIdx.x;
    int r = tid >> 3, cg = tid & 7, col0 = half*32 + cg*4;
    int grow = chunk*32 + r;
    __shared__ float xmc[16*64];
    const float* xmbase = g_xm + ((size_t)(branch*16 + b)*256)*64;

    const float* wbase; float sA, bA;
    if (grow < 128)      { wbase = Wq + grow*256;       sA = sq[grow];     bA = bq[grow]; }
    else if (grow < 256) { wbase = Wk + (grow-128)*256; sA = sk[grow-128]; bA = bk[grow-128]; }
    else                 { wbase = Wv + (grow-256)*256; sA = sv[grow-256]; bA = bv[grow-256]; }

    float acc[4] = {0.f, 0.f, 0.f, 0.f};

    for (int kc = 0; kc < 16; kc++) {
        #pragma unroll
        for (int t = 0; t < 4; t++) {
            int idx = tid + t*256;
            xmc[idx] = xmbase[(kc*16 + (idx >> 6))*64 + (idx & 63)];
        }
        __syncthreads();
        #pragma unroll
        for (int kk = 0; kk < 16; kk++) {
            float wv = wbase[kc*16 + kk];
            float4 b0 = *(const float4*)&xmc[kk*64 + col0];
            acc[0] = fmaf(wv, b0.x, acc[0]); acc[1] = fmaf(wv, b0.y, acc[1]);
            acc[2] = fmaf(wv, b0.z, acc[2]); acc[3] = fmaf(wv, b0.w, acc[3]);
        }
        __syncthreads();
    }

    float outv[4];
    #pragma unroll
    for (int j = 0; j < 4; j++) outv[j] = fmaf(sA, acc[j], bA);

    if (grow < 256) {
        const float* pe = (branch == 0) ? ((grow < 128) ? pe_rq : pe_rk)
                                        : ((grow < 128) ? pe_cq : pe_ck);
        int chan = (grow < 128) ? grow : grow - 128;
        #pragma unroll
        for (int j = 0; j < 4; j++) outv[j] += pe_interp(pe, chan, col0 + j);
    }
    float* dst = g_qkm + ((size_t)((branch*16 + b)*512 + grow))*64 + col0;
    #pragma unroll
    for (int j = 0; j < 4; j++) dst[j] = outv[j];
}

// ---------------------------------------------------------------------------
// K2b: fused attention + Wr/Wc projection. grid (2 branch, 16 b), 256 thr.
// smem: att[256][64] | kf_all[128][64] | vf_all[256][64]
// ---------------------------------------------------------------------------
#define AP_SMEM_FLOATS (16384 + 8192 + 16384)
#define AP_SMEM_BYTES  (AP_SMEM_FLOATS*4)

__global__ void k_attnproj(
    const float* __restrict__ Wr, const float* __restrict__ sr, const float* __restrict__ br,
    const float* __restrict__ Wc, const float* __restrict__ sc, const float* __restrict__ bc)
{
    extern __shared__ float sm[];
    float* att    = sm;             // [256][64]
    float* kf_all = sm + 16384;     // [128][64]
    float* vf_all = sm + 24576;     // [256][64]

    int branch = blockIdx.x;
    int b      = blockIdx.y;
    int tid = threadIdx.x;
    const float* base = g_qkm + ((size_t)(branch*16 + b)*512)*64;

    for (int idx = tid; idx < 8192; idx += 256)  kf_all[idx] = base[128*64 + idx];
    for (int idx = tid; idx < 16384; idx += 256) vf_all[idx] = base[256*64 + idx];
    __syncthreads();

    // ---- attention: head = tid>>5, lane handles queries l and l+32 ----
    int h2 = tid >> 5, l = tid & 31;
    const float* kf = kf_all + h2*1024;
    const float* vf = vf_all + h2*2048;
    #pragma unroll 1
    for (int qi = 0; qi < 2; qi++) {
        int q = l + qi*32;
        float qv[16];
        #pragma unroll
        for (int kd = 0; kd < 16; kd++) qv[kd] = base[(h2*16 + kd)*64 + q];

        float mx = -1e30f;
        for (int j = 0; j < 64; j++) {
            float s = 0.f;
            #pragma unroll
            for (int kd = 0; kd < 16; kd++) s = fmaf(qv[kd], kf[kd*64 + j], s);
            mx = fmaxf(mx, s * 0.25f);
        }
        float sum = 0.f;
        float facc[32];
        #pragma unroll
        for (int d = 0; d < 32; d++) facc[d] = 0.f;
        for (int j = 0; j < 64; j++) {
            float s = 0.f;
            #pragma unroll
            for (int kd = 0; kd < 16; kd++) s = fmaf(qv[kd], kf[kd*64 + j], s);
            float e = expf(s * 0.25f - mx);
            sum += e;
            #pragma unroll
            for (int d = 0; d < 32; d++) facc[d] = fmaf(e, vf[d*64 + j], facc[d]);
        }
        float inv = 1.f / sum;
        #pragma unroll
        for (int d = 0; d < 32; d++)
            att[(h2*32 + d)*64 + q] = fmaxf(facc[d]*inv, 0.f);
    }
    __syncthreads();

    // ---- projection: 256 out-rows x 64 cols, K=256, A in smem ----
    int r = tid >> 3, cg = tid & 7, col0 = cg*8;
    const float* Wsel = branch ? Wc : Wr;
    const float* ssel = branch ? sc : sr;
    const float* bsel = branch ? bc : br;

    #pragma unroll 1
    for (int chunk = 0; chunk < 8; chunk++) {
        int grow = chunk*32 + r;
        const float4* wrow = (const float4*)(Wsel + (size_t)grow*256);
        float sA = ssel[grow], bA = bsel[grow];
        float acc[8];
        #pragma unroll
        for (int j = 0; j < 8; j++) acc[j] = 0.f;
        #pragma unroll 4
        for (int k4 = 0; k4 < 64; k4++) {
            float4 wv4 = wrow[k4];
            float wvs[4] = {wv4.x, wv4.y, wv4.z, wv4.w};
            #pragma unroll
            for (int s2 = 0; s2 < 4; s2++) {
                int k = k4*4 + s2;
                float4 a0 = *(const float4*)&att[k*64 + col0];
                float4 a1 = *(const float4*)&att[k*64 + col0 + 4];
                float wv = wvs[s2];
                acc[0] = fmaf(wv, a0.x, acc[0]); acc[1] = fmaf(wv, a0.y, acc[1]);
                acc[2] = fmaf(wv, a0.z, acc[2]); acc[3] = fmaf(wv, a0.w, acc[3]);
                acc[4] = fmaf(wv, a1.x, acc[4]); acc[5] = fmaf(wv, a1.y, acc[5]);
                acc[6] = fmaf(wv, a1.z, acc[6]); acc[7] = fmaf(wv, a1.w, acc[7]);
            }
        }
        float* dst = g_xrc + ((size_t)((branch*16 + b)*256 + grow))*64 + col0;
        #pragma unroll
        for (int j = 0; j < 8; j++) dst[j] = fmaf(sA, acc[j], bA);
    }
}

// ===========================================================================
// K3: TF32 tensor-core fused main kernel. M=32 pixels/block, 2048 blocks,
// 2 blocks/SM. Per pass N=256, K=256 (stage2 split into two K=256 halves).
// A: smem [pixel][k] stride 260 (CF banks); B: [n][20] double-buffered.
// ===========================================================================
#define XSTR 260
#define WPAD 20
#define WBUF 5120
#define OFF_X  0          // [32][260] x (tf32), later v_raw (fp32)
#define OFF_P  8320       // [32][260] stage outputs (tf32)
#define OFF_W  16640      // 2 x [256][20]
#define OFF_AL 26880
#define OFF_BE 27392
#define OFF_XR 27904
#define K3_SMEM_FLOATS 28160
#define K3_SMEM_BYTES (K3_SMEM_FLOATS*4)

__device__ __forceinline__ float tf32r(float x) {
    uint32_t u;
    asm("cvt.rna.tf32.f32 %0, %1;" : "=r"(u) : "f"(x));
    return __uint_as_float(u);
}

__device__ __forceinline__ void wload(float4 pf[4], const float* W0, const float* W1,
                                      int kstride, int k0, int quad, int nb) {
    #pragma unroll
    for (int r = 0; r < 4; r++) {
        int n = nb + r*64;
        const float* base = (r < 2) ? (W0 + (size_t)n*kstride)
                                    : (W1 + (size_t)(n-128)*kstride);
        pf[r] = *(const float4*)(base + k0 + quad*4);
    }
}

__device__ __forceinline__ void wstore(const float4 pf[4], float* sWb, int quad, int nb) {
    #pragma unroll
    for (int r = 0; r < 4; r++) {
        int n = nb + r*64;
        float4 v;
        v.x = tf32r(pf[r].x); v.y = tf32r(pf[r].y);
        v.z = tf32r(pf[r].z); v.w = tf32r(pf[r].w);
        *(float4*)&sWb[n*WPAD + quad*4] = v;
    }
}

__device__ __forceinline__ void gemm_iter(const float* A, const float* sWb,
                                          int nw, int g, int tig,
                                          float (&acc)[2][4][4]) {
    #pragma unroll
    for (int ks2 = 0; ks2 < 2; ks2++) {
        int kk = ks2*8;
        uint32_t a[2][4];
        #pragma unroll
        for (int m = 0; m < 2; m++) {
            int r0 = m*16 + g;
            a[m][0] = __float_as_uint(A[r0*XSTR + kk + tig]);
            a[m][1] = __float_as_uint(A[(r0+8)*XSTR + kk + tig]);
            a[m][2] = __float_as_uint(A[r0*XSTR + kk + tig + 4]);
            a[m][3] = __float_as_uint(A[(r0+8)*XSTR + kk + tig + 4]);
        }
        #pragma unroll
        for (int nt = 0; nt < 4; nt++) {
            int n0 = nw + nt*8;
            uint32_t b0 = __float_as_uint(sWb[(n0+g)*WPAD + kk + tig]);
            uint32_t b1 = __float_as_uint(sWb[(n0+g)*WPAD + kk + tig + 4]);
            #pragma unroll
            for (int m = 0; m < 2; m++) {
                asm volatile(
                    "mma.sync.aligned.m16n8k8.row.col.f32.tf32.tf32.f32 "
                    "{%0,%1,%2,%3}, {%4,%5,%6,%7}, {%8,%9}, {%0,%1,%2,%3};"
                    : "+f"(acc[m][nt][0]), "+f"(acc[m][nt][1]),
                      "+f"(acc[m][nt][2]), "+f"(acc[m][nt][3])
                    : "r"(a[m][0]), "r"(a[m][1]), "r"(a[m][2]), "r"(a[m][3]),
                      "r"(b0), "r"(b1));
            }
        }
    }
}

// 16 K-chunks (K=256), double-buffered weights: 1 barrier per chunk.
__device__ __forceinline__ void run_gemm(const float* A,
                                         const float* W0, const float* W1, int kstride,
                                         float* sW, float (&acc)[2][4][4],
                                         int tid, int nw, int g, int tig) {
    int quad = tid & 3, nb = tid >> 2;
    float4 pf[4];
    wload(pf, W0, W1, kstride, 0, quad, nb);
    wstore(pf, sW, quad, nb);
    wload(pf, W0, W1, kstride, 16, quad, nb);
    __syncthreads();
    #pragma unroll 1
    for (int it = 0; it < 16; it++) {
        float* cur = sW + (it & 1)*WBUF;
        if (it < 15) {
            wstore(pf, sW + ((it + 1) & 1)*WBUF, quad, nb);
            if (it < 14) wload(pf, W0, W1, kstride, (it + 2)*16, quad, nb);
        }
        gemm_iter(A + it*16, cur, nw, g, tig, acc);
        __syncthreads();
    }
}

__global__ void __launch_bounds__(256, 2) k_main(
    const float* __restrict__ x,
    const float* __restrict__ Wq, const float* __restrict__ Wk, const float* __restrict__ Wv,
    const float* __restrict__ sq, const float* __restrict__ bq,
    const float* __restrict__ sk, const float* __restrict__ bk,
    const float* __restrict__ sv, const float* __restrict__ bv,
    const float* __restrict__ wdw, const float* __restrict__ sdw, const float* __restrict__ bdw,
    const float* __restrict__ Wpw, const float* __restrict__ spw, const float* __restrict__ bpw,
    const float* __restrict__ Wp,  const float* __restrict__ sp,  const float* __restrict__ bp,
    float* __restrict__ out)
{
    extern __shared__ float sm[];
    float* sX  = sm + OFF_X;
    float* sP  = sm + OFF_P;
    float* sW  = sm + OFF_W;
    float* al  = sm + OFF_AL;
    float* be  = sm + OFF_BE;
    float* xrs = sm + OFF_XR;

    int bx = blockIdx.x;
    int b  = bx >> 7;
    int h  = (bx >> 1) & 63;
    int wh = bx & 1;
    int tid = threadIdx.x;
    int lane = tid & 31, warp = tid >> 5;
    int g = lane >> 2, tig = lane & 3;
    int nw = warp * 32;

    // ---- load x tile [32 pixels][256 ch] (tf32) + al/be + xr ----
    const float* xb = x + (size_t)b*256*NPIX + h*64 + wh*32;
    #pragma unroll 4
    for (int t = 0; t < 32; t++) {
        int idx = tid + t*256;
        int c = idx >> 5, p = idx & 31;
        sX[p*XSTR + c] = tf32r(xb[c*NPIX + p]);
    }
    for (int ch = tid; ch < 512; ch += 256) {
        float s, bb;
        if (ch < 128)      { s = sq[ch];     bb = bq[ch]; }
        else if (ch < 256) { s = sk[ch-128]; bb = bk[ch-128]; }
        else               { s = sv[ch-256]; bb = bv[ch-256]; }
        float e = wdw[ch]*sdw[ch];
        al[ch] = e*s;
        be[ch] = fmaf(e, bb, bdw[ch]);
    }
    xrs[tid] = g_xrc[((size_t)b*256 + tid)*64 + h];
    __syncthreads();

    float acc[2][4][4];
    float gacc[2][4][4];
    #pragma unroll
    for (int m = 0; m < 2; m++)
        #pragma unroll
        for (int nt = 0; nt < 4; nt++)
            #pragma unroll
            for (int e = 0; e < 4; e++) { acc[m][nt][e] = 0.f; gacc[m][nt][e] = 0.f; }

    // ========== stage1 pass1: qk rows (out 0..255) ==========
    run_gemm(sX, Wq, Wk, 256, sW, acc, tid, nw, g, tig);
    #pragma unroll
    for (int m = 0; m < 2; m++)
        #pragma unroll
        for (int nt = 0; nt < 4; nt++) {
            int ch = nw + nt*8 + 2*tig;
            int p0 = m*16 + g;
            #pragma unroll
            for (int e = 0; e < 4; e++) {
                int che = ch + (e & 1);
                int pe  = p0 + ((e >> 1) << 3);
                sP[pe*XSTR + che] = tf32r(fmaxf(fmaf(al[che], acc[m][nt][e], be[che]), 0.f));
            }
        }
    __syncthreads();

    // ========== stage2a: gate += P_qk @ Wpw[:, 0:256]^T ==========
    run_gemm(sP, Wpw, Wpw + (size_t)128*512, 512, sW, gacc, tid, nw, g, tig);

    // ========== stage1 pass2: v rows ==========
    #pragma unroll
    for (int m = 0; m < 2; m++)
        #pragma unroll
        for (int nt = 0; nt < 4; nt++)
            #pragma unroll
            for (int e = 0; e < 4; e++) acc[m][nt][e] = 0.f;
    run_gemm(sX, Wv, Wv + (size_t)128*256, 256, sW, acc, tid, nw, g, tig);
    #pragma unroll
    for (int m = 0; m < 2; m++)
        #pragma unroll
        for (int nt = 0; nt < 4; nt++) {
            int ch = nw + nt*8 + 2*tig;
            int p0 = m*16 + g;
            #pragma unroll
            for (int e = 0; e < 4; e++) {
                int che = ch + (e & 1);
                int pe  = p0 + ((e >> 1) << 3);
                float rr = acc[m][nt][e];
                sP[pe*XSTR + che] = tf32r(fmaxf(fmaf(al[256+che], rr, be[256+che]), 0.f));
                sX[pe*XSTR + che] = fmaf(sv[che], rr, bv[che]);   // v_raw (fp32)
            }
        }
    __syncthreads();

    // ========== stage2b: gate += P_v @ Wpw[:, 256:512]^T ==========
    run_gemm(sP, Wpw + 256, Wpw + (size_t)128*512 + 256, 512, sW, gacc, tid, nw, g, tig);

    // ========== y = relu(v_raw + xr + xc) -> P ==========
    const float* xcb = g_xrc + ((size_t)(16 + b))*16384;
    #pragma unroll 4
    for (int t = 0; t < 32; t++) {
        int idx = tid + t*256;
        int p = idx & 31, ch = idx >> 5;
        float y = fmaxf(sX[p*XSTR + ch] + xrs[ch] + xcb[ch*64 + wh*32 + p], 0.f);
        sP[p*XSTR + ch] = tf32r(y);
    }
    __syncthreads();

    // ========== stage3: o = Y @ Wp^T ==========
    #pragma unroll
    for (int m = 0; m < 2; m++)
        #pragma unroll
        for (int nt = 0; nt < 4; nt++)
            #pragma unroll
            for (int e = 0; e < 4; e++) acc[m][nt][e] = 0.f;
    run_gemm(sP, Wp, Wp + (size_t)128*256, 256, sW, acc, tid, nw, g, tig);

    // ========== final epilogue: hsigmoid(sp*o+bp) * (spw*gate+bpw) ==========
    #pragma unroll
    for (int m = 0; m < 2; m++)
        #pragma unroll
        for (int nt = 0; nt < 4; nt++) {
            int ch = nw + nt*8 + 2*tig;
            int p0 = m*16 + g;
            float s0 = sp[ch],  s1 = sp[ch+1];
            float bb0 = bp[ch], bb1 = bp[ch+1];
            float gs0 = spw[ch], gs1 = spw[ch+1];
            float gb0 = bpw[ch], gb1 = bpw[ch+1];
            #pragma unroll
            for (int e = 0; e < 4; e++) {
                int odd = e & 1;
                int che = ch + odd;
                int pe  = p0 + ((e >> 1) << 3);
                float o  = fmaf(odd ? s1 : s0, acc[m][nt][e], odd ? bb1 : bb0);
                float hs = fminf(fmaxf(o + 3.f, 0.f), 6.f) * (1.f/6.f);
                float gt = fmaf(odd ? gs1 : gs0, gacc[m][nt][e], odd ? gb1 : gb0);
                out[((size_t)(b*256 + che))*NPIX + h*64 + wh*32 + pe] = hs * gt;
            }
        }
}

// ---------------------------------------------------------------------------
extern "C" void kernel_launch(void* const* d_in, const int* in_sizes, int n_in,
                              void* d_out, int out_size) {
    const float* x     = (const float*)d_in[0];
    const float* Wq    = (const float*)d_in[1];
    const float* sq    = (const float*)d_in[2];
    const float* bq    = (const float*)d_in[3];
    const float* Wk    = (const float*)d_in[4];
    const float* sk    = (const float*)d_in[5];
    const float* bk    = (const float*)d_in[6];
    const float* Wv    = (const float*)d_in[7];
    const float* sv    = (const float*)d_in[8];
    const float* bv    = (const float*)d_in[9];
    const float* pe_rq = (const float*)d_in[10];
    const float* pe_rk = (const float*)d_in[11];
    const float* pe_cq = (const float*)d_in[12];
    const float* pe_ck = (const float*)d_in[13];
    const float* wdw   = (const float*)d_in[14];
    const float* sdw   = (const float*)d_in[15];
    const float* bdw   = (const float*)d_in[16];
    const float* Wpw   = (const float*)d_in[17];
    const float* spw   = (const float*)d_in[18];
    const float* bpw   = (const float*)d_in[19];
    const float* Wr    = (const float*)d_in[20];
    const float* sr    = (const float*)d_in[21];
    const float* br    = (const float*)d_in[22];
    const float* Wc    = (const float*)d_in[23];
    const float* sc    = (const float*)d_in[24];
    const float* bc    = (const float*)d_in[25];
    const float* Wp    = (const float*)d_in[26];
    const float* sp    = (const float*)d_in[27];
    const float* bp    = (const float*)d_in[28];
    float* out = (float*)d_out;

    cudaFuncSetAttribute(k_main, cudaFuncAttributeMaxDynamicSharedMemorySize, K3_SMEM_BYTES);
    cudaFuncSetAttribute(k_attnproj, cudaFuncAttributeMaxDynamicSharedMemorySize, AP_SMEM_BYTES);

    k_means<<<4096, 64>>>(x);
    k_projmean<<<dim3(32, 2, 16), 256>>>(Wq, sq, bq, Wk, sk, bk, Wv, sv, bv,
                                         pe_rq, pe_rk, pe_cq, pe_ck);
    k_attnproj<<<dim3(2, 16), 256, AP_SMEM_BYTES>>>(Wr, sr, br, Wc, sc, bc);
    k_main<<<2048, 256, K3_SMEM_BYTES>>>(x, Wq, Wk, Wv, sq, bq, sk, bk, sv, bv,
                                         wdw, sdw, bdw, Wpw, spw, bpw, Wp, sp, bp, out);
}